// round 8
// baseline (speedup 1.0000x reference)
#include <cuda_runtime.h>
#include <cstdint>

// NAIS scoring via warp-level tf32 mma.sync + cp.async double-buffered staging.
//
//   qp[d]  = bias[h,d] + sum_e Q[b,h,e] * Wc[h,e,d]            (fp32, exact)
//   out[k] = sum_d relu( qp[d] + (K[k,:] @ Wk)[d] ) * Wo[h,d]  (K@Wk in tf32)
//
// m16n8k8 fragments (g = lane>>2, c = lane&3):
//   A: a0=(g,s0) a1=(g+8,s0) a2=(g,s1) a3=(g+8,s1);  B: b0=(s0,n=g) b1=(s1,n=g)
//   C: c0=(g,2c) c1=(g,2c+1) c2=(g+8,2c) c3=(g+8,2c+1)
// Line-dense column permutation (same bijection on A and B), step s = 2j+t:
//   slot0 -> col 16j + 4c + 2t, slot1 -> +1  => thread's j-th float4 = row
//   bytes [64j+16c, +16), i.e. A[hf][4j+u] = element u of float4 j.
//
// Pipeline: 128-row tiles cp.async.cg'd (L1-bypass) into 2 smem buffers, 2 tiles
// in flight. Smem row stride 320B -> LDS.128 A-fragment reads conflict-free
// (row r base bank = 16r mod 32; each 8-lane phase covers banks 0..31 once).
// Warps own 16 rows/iter -> A = 32 regs (no spill; R5/R6's 64-reg trap gone).

namespace {
constexpr int Bc = 32, Hc = 8, KL = 8192, Dd = 64;
constexpr int NTHREADS = 256;                 // 8 warps
constexpr int TILE     = 128;                 // rows per CTA tile
constexpr int KCHUNK   = 2048;                // rows per CTA
constexpr int NT       = KCHUNK / TILE;       // 16 tiles
constexpr int RSTRIDE  = 80;                  // floats per smem row (320 B)

constexpr int KBUF_BYTES = TILE * RSTRIDE * 4;        // 40960 per buffer
constexpr int OFF_KBUF   = 0;                          // 2 buffers
constexpr int OFF_BP     = 2 * KBUF_BYTES;             // 81920
constexpr int OFF_QPS    = OFF_BP + 8 * 8 * 32 * 8;    // +16384 = 98304
constexpr int OFF_WOS    = OFF_QPS + 256;
constexpr int SMEM_TOTAL = OFF_WOS + 256;              // 98816 B -> 2 CTAs/SM
}

__device__ __forceinline__ uint32_t f2tf(float f) {
    uint32_t r;
    asm("cvt.rna.tf32.f32 %0, %1;" : "=r"(r) : "f"(f));
    return r;
}

__device__ __forceinline__ uint32_t smem_u32(const void* p) {
    uint32_t a;
    asm("{ .reg .u64 t; cvta.to.shared.u64 t, %1; cvt.u32.u64 %0, t; }" : "=r"(a) : "l"(p));
    return a;
}

__device__ __forceinline__ void cp_async16(uint32_t saddr, const void* gaddr) {
    asm volatile("cp.async.cg.shared.global [%0], [%1], 16;" :: "r"(saddr), "l"(gaddr));
}
#define CP_COMMIT() asm volatile("cp.async.commit_group;" ::: "memory")

__device__ __forceinline__ void mma_tf32(float c[4],
                                         uint32_t a0, uint32_t a1, uint32_t a2, uint32_t a3,
                                         uint32_t b0, uint32_t b1) {
    asm volatile(
        "mma.sync.aligned.m16n8k8.row.col.f32.tf32.tf32.f32 "
        "{%0,%1,%2,%3}, {%4,%5,%6,%7}, {%8,%9}, {%0,%1,%2,%3};"
        : "+f"(c[0]), "+f"(c[1]), "+f"(c[2]), "+f"(c[3])
        : "r"(a0), "r"(a1), "r"(a2), "r"(a3), "r"(b0), "r"(b1));
}

__global__ void __launch_bounds__(NTHREADS, 2)
nais_cp_kernel(const float* __restrict__ Q, const float* __restrict__ K,
               const float* __restrict__ Wc, const float* __restrict__ Wo,
               const float* __restrict__ bias, float* __restrict__ out)
{
    extern __shared__ __align__(16) char smem[];
    const uint32_t sb = smem_u32(smem);
    uint2*  Bp  = reinterpret_cast<uint2*>(smem + OFF_BP);
    float*  qps = reinterpret_cast<float*>(smem + OFF_QPS);
    float*  wos = reinterpret_cast<float*>(smem + OFF_WOS);

    const int tid  = threadIdx.x;
    const int w    = tid >> 5;
    const int lane = tid & 31;
    const int c    = lane & 3;
    const int g    = lane >> 2;

    const int bid   = blockIdx.x;
    const int bh    = bid >> 2;               // b*H + h
    const int chunk = bid & 3;
    const int h     = bh & (Hc - 1);

    const float* __restrict__ WcH = Wc + (size_t)h * 2 * Dd * Dd;
    const float* __restrict__ Wk  = WcH + Dd * Dd;
    const float* __restrict__ Kc  = K + (size_t)bh * KL * Dd + (size_t)chunk * KCHUNK * Dd;
    float* __restrict__ outp = out + (size_t)bh * KL + (size_t)chunk * KCHUNK;

    // ---- stage tile t into buffer buf: 8 x 16B chunks per thread ----
    #define ISSUE_TILE(t_, buf_) do {                                              \
        const float* _src = Kc + (size_t)(t_) * TILE * Dd;                         \
        const uint32_t _sB = sb + OFF_KBUF + (buf_) * KBUF_BYTES;                  \
        _Pragma("unroll")                                                          \
        for (int _i = 0; _i < 8; _i++) {                                           \
            int _ch = tid + _i * NTHREADS;     /* 0..2047 */                       \
            int _r = _ch >> 4, _j = _ch & 15;                                      \
            cp_async16(_sB + _r * (RSTRIDE * 4) + _j * 16,                         \
                       _src + (size_t)_r * Dd + _j * 4);                           \
        }                                                                          \
        CP_COMMIT();                                                               \
    } while (0)

    // ---- prologue: Bp pack (line-dense map), qp, wo; pipeline prime ----
    ISSUE_TILE(0, 0);
    ISSUE_TILE(1, 1);

    #pragma unroll
    for (int i = 0; i < (8 * 8 * 32) / NTHREADS; i++) {
        int idx = tid + i * NTHREADS;          // ((nt*8 + s)*32 + ln)
        int ln = idx & 31, s = (idx >> 5) & 7, nt = idx >> 8;
        int cc = ln & 3, gg = ln >> 2;
        int e0 = 16 * (s >> 1) + 4 * cc + 2 * (s & 1);   // line-dense map
        int n  = nt * 8 + gg;
        Bp[idx] = make_uint2(f2tf(Wk[e0 * Dd + n]), f2tf(Wk[(e0 + 1) * Dd + n]));
    }
    if (tid < Dd) {
        wos[tid] = Wo[h * Dd + tid];
        float acc = bias[h * Dd + tid];
        const float* __restrict__ q = Q + (size_t)bh * Dd;
        #pragma unroll 8
        for (int e = 0; e < Dd; e++) acc = fmaf(q[e], WcH[e * Dd + tid], acc);
        qps[tid] = acc;
    }
    __syncthreads();

    // ---- main loop ----
    for (int t = 0; t < NT; t++) {
        const int buf = t & 1;

        if (t == NT - 1) asm volatile("cp.async.wait_group 0;" ::: "memory");
        else             asm volatile("cp.async.wait_group 1;" ::: "memory");
        __syncthreads();

        // A fragments: warp rows w*16 + hf*8 + g; LDS.128 at j*64 + c*16 (conflict-free)
        const uint32_t rowAddr = sb + OFF_KBUF + buf * KBUF_BYTES
                               + (w * 16 + g) * (RSTRIDE * 4) + c * 16;
        uint32_t A[2][16];
        #pragma unroll
        for (int hf = 0; hf < 2; hf++) {
            #pragma unroll
            for (int j = 0; j < 4; j++) {
                uint32_t x, y, z, u;
                asm volatile("ld.shared.v4.b32 {%0,%1,%2,%3}, [%4];"
                             : "=r"(x), "=r"(y), "=r"(z), "=r"(u)
                             : "r"(rowAddr + hf * 8 * (RSTRIDE * 4) + j * 64));
                A[hf][4 * j + 0] = f2tf(__uint_as_float(x));
                A[hf][4 * j + 1] = f2tf(__uint_as_float(y));
                A[hf][4 * j + 2] = f2tf(__uint_as_float(z));
                A[hf][4 * j + 3] = f2tf(__uint_as_float(u));
            }
        }

        float psum[2] = {0.f, 0.f};
        #pragma unroll
        for (int nt = 0; nt < 8; nt++) {
            const float qp0 = qps[nt * 8 + 2 * c], qp1 = qps[nt * 8 + 2 * c + 1];
            const float w0  = wos[nt * 8 + 2 * c], w1  = wos[nt * 8 + 2 * c + 1];
            float acc[4] = {0.f, 0.f, 0.f, 0.f};
            #pragma unroll
            for (int s = 0; s < 8; s++) {
                const uint2 b = Bp[(nt * 8 + s) * 32 + lane];
                mma_tf32(acc, A[0][2 * s], A[1][2 * s],
                              A[0][2 * s + 1], A[1][2 * s + 1], b.x, b.y);
            }
            psum[0] += fmaxf(acc[0] + qp0, 0.f) * w0 + fmaxf(acc[1] + qp1, 0.f) * w1;
            psum[1] += fmaxf(acc[2] + qp0, 0.f) * w0 + fmaxf(acc[3] + qp1, 0.f) * w1;
        }

        #pragma unroll
        for (int hf = 0; hf < 2; hf++) {
            float p = psum[hf];
            p += __shfl_xor_sync(0xffffffffu, p, 1);
            p += __shfl_xor_sync(0xffffffffu, p, 2);
            if (c == 0)
                outp[t * TILE + w * 16 + hf * 8 + g] = p;
        }

        __syncthreads();                       // all warps done with buf before refill
        if (t + 2 < NT) ISSUE_TILE(t + 2, buf);
        else            CP_COMMIT();           // keep group counting uniform
    }
    #undef ISSUE_TILE
}

extern "C" void kernel_launch(void* const* d_in, const int* in_sizes, int n_in,
                              void* d_out, int out_size)
{
    const float* Q    = (const float*)d_in[0];
    const float* K    = (const float*)d_in[1];
    const float* Wc   = (const float*)d_in[2];
    const float* Wo   = (const float*)d_in[3];
    const float* bias = (const float*)d_in[4];
    float* out = (float*)d_out;

    cudaFuncSetAttribute(nais_cp_kernel,
                         cudaFuncAttributeMaxDynamicSharedMemorySize, SMEM_TOTAL);

    const int grid = Bc * Hc * (KL / KCHUNK);   // 1024 blocks
    nais_cp_kernel<<<grid, NTHREADS, SMEM_TOTAL>>>(Q, K, Wc, Wo, bias, out);
}